// round 15
// baseline (speedup 1.0000x reference)
#include <cuda_runtime.h>
#include <cuda_fp16.h>
#include <stdint.h>
#include <math.h>

// ---------------- problem constants ----------------
#define T_TOKENS 8192          // 4 * 2048
#define DD 1024                // emb dim
#define HH 4096                // hidden dim
#define EE 8                   // experts
#define PAIRS (T_TOKENS * 2)   // 16384 routed (token, expert) pairs

// ---------------- device scratch: proven footprint; NO weight copies ----------
__device__ int   g_count[EE];
__device__ int   g_ek[PAIRS];
__device__ int   g_slot[PAIRS];
__device__ float g_gate[PAIRS];
__device__ int   g_row[PAIRS];     // per (t,k): compact row id
__device__ int   g_tok[PAIRS];     // per compact row: token id
__device__ float g_hid[(size_t)PAIRS * HH];     // head 134 MB used as fp16 hid
__device__ float g_y  [(size_t)PAIRS * DD];     // head 16.7 MB = x fp16 alias

#define HID_H   (reinterpret_cast<__half*>(g_hid))
#define XH      (reinterpret_cast<__half*>(g_y))

// ---------------- helpers ----------------
__device__ __forceinline__ uint32_t smem_u32(const void* p) {
    uint32_t a;
    asm("{ .reg .u64 t; cvta.to.shared.u64 t, %1; cvt.u32.u64 %0, t; }" : "=r"(a) : "l"(p));
    return a;
}
__device__ __forceinline__ void cp_async16(uint32_t dst, const void* src) {
    asm volatile("cp.async.cg.shared.global [%0], [%1], 16;" :: "r"(dst), "l"(src));
}
__device__ __forceinline__ void cp_commit() {
    asm volatile("cp.async.commit_group;" ::: "memory");
}
template <int N>
__device__ __forceinline__ void cp_wait() {
    asm volatile("cp.async.wait_group %0;" :: "n"(N) : "memory");
}
__device__ __forceinline__ uint32_t pack_h2(float lo, float hi) {
    __half2 h = __floats2half2_rn(lo, hi);      // low 16 bits = lo
    return *reinterpret_cast<uint32_t*>(&h);
}
__device__ __forceinline__ void mma_f16(float* d, const uint32_t* a, const uint32_t* b) {
    asm volatile(
        "mma.sync.aligned.m16n8k16.row.col.f32.f16.f16.f32 "
        "{%0,%1,%2,%3}, {%4,%5,%6,%7}, {%8,%9}, {%0,%1,%2,%3};"
        : "+f"(d[0]), "+f"(d[1]), "+f"(d[2]), "+f"(d[3])
        : "r"(a[0]), "r"(a[1]), "r"(a[2]), "r"(a[3]), "r"(b[0]), "r"(b[1]));
}
__device__ __forceinline__ void ldsm_x4(uint32_t* r, uint32_t addr) {
    asm volatile("ldmatrix.sync.aligned.m8n8.x4.shared.b16 {%0,%1,%2,%3}, [%4];"
                 : "=r"(r[0]), "=r"(r[1]), "=r"(r[2]), "=r"(r[3]) : "r"(addr));
}
__device__ __forceinline__ int expert_offset(int e) {
    int s = 0;
#pragma unroll
    for (int i = 0; i < EE; i++) if (i < e) s += g_count[i];
    return s;
}

// ---------------- kernel 0: zero counters ----------------
__global__ void zero_counts_kernel() {
    if (threadIdx.x < EE) g_count[threadIdx.x] = 0;
}

// ---------------- kernel 1: router (1 warp/token) + fused x->fp16 ------------
__global__ void router_kernel(const float* __restrict__ x,
                              const float* __restrict__ wr,
                              const float* __restrict__ br) {
    int warp = (blockIdx.x * blockDim.x + threadIdx.x) >> 5;
    int lane = threadIdx.x & 31;
    if (warp >= T_TOKENS) return;
    const float* xr = x + (size_t)warp * DD;
    __half* xh = XH + (size_t)warp * DD;

    float acc[EE];
#pragma unroll
    for (int e = 0; e < EE; e++) acc[e] = 0.f;
#pragma unroll 4
    for (int c = 0; c < DD / 32; c++) {
        int k = c * 32 + lane;
        float xv = __ldg(xr + k);
        xh[k] = __float2half_rn(xv);             // fused fp16 conversion
        const float4* w4 = reinterpret_cast<const float4*>(wr + (size_t)k * EE);
        float4 a = __ldg(&w4[0]);
        float4 b = __ldg(&w4[1]);
        acc[0] += xv * a.x; acc[1] += xv * a.y; acc[2] += xv * a.z; acc[3] += xv * a.w;
        acc[4] += xv * b.x; acc[5] += xv * b.y; acc[6] += xv * b.z; acc[7] += xv * b.w;
    }
#pragma unroll
    for (int e = 0; e < EE; e++)
#pragma unroll
        for (int o = 16; o > 0; o >>= 1)
            acc[e] += __shfl_down_sync(0xffffffffu, acc[e], o);

    if (lane == 0) {
        float l[EE];
        float mx = -1e30f;
#pragma unroll
        for (int e = 0; e < EE; e++) { l[e] = acc[e] + br[e]; mx = fmaxf(mx, l[e]); }
        float s = 0.f;
#pragma unroll
        for (int e = 0; e < EE; e++) { l[e] = expf(l[e] - mx); s += l[e]; }
        float inv = 1.0f / s;
        int e0 = 0;
#pragma unroll
        for (int e = 1; e < EE; e++) if (l[e] > l[e0]) e0 = e;
        int e1 = (e0 == 0) ? 1 : 0;
#pragma unroll
        for (int e = 0; e < EE; e++) if (e != e0 && l[e] > l[e1]) e1 = e;
        int t = warp;
        int s0 = atomicAdd(&g_count[e0], 1);
        g_ek[t * 2 + 0] = e0; g_slot[t * 2 + 0] = s0; g_gate[t * 2 + 0] = l[e0] * inv;
        int s1 = atomicAdd(&g_count[e1], 1);
        g_ek[t * 2 + 1] = e1; g_slot[t * 2 + 1] = s1; g_gate[t * 2 + 1] = l[e1] * inv;
    }
}

// ---------------- kernel 2: scatter compact rows (offsets inline) ------------
__global__ void scatter_kernel() {
    int i = blockIdx.x * blockDim.x + threadIdx.x;
    if (i >= PAIRS) return;
    int e = g_ek[i];
    int row = expert_offset(e) + g_slot[i];
    g_row[i] = row;
    g_tok[row] = i >> 1;
}

// ---------------- grouped GEMM: m16n8k16 fp16, CTA 256x128x32, 512 thr -------
// 16 warps (4m x 4n) of 64x32 -> same 16 warps/SM as occ-2 config but B-fill
// and sync cost halve per FLOP. A via cp.async + ldmatrix; B via hoisted LDG
// fp32 from HARNESS weights -> pack half2 -> STS.
constexpr int BM = 256, BN = 128, BK = 32;   // BK in k-elements
constexpr int A_STR_U = 20;                  // 40 fp16 = 80 B row stride
constexpr int B_STR_U = 136;                 // u32 stride per k-pair row
constexpr int A_TILE_U = BM * A_STR_U;       // 5120 u32
constexpr int B_TILE_U = (BK / 2) * B_STR_U; // 2176 u32
constexpr int STAGE_U  = A_TILE_U + B_TILE_U;
constexpr int GEMM_SMEM = 2 * STAGE_U * 4;   // 58368 bytes

template <int NN, int KK, bool FFN1>
__global__ void __launch_bounds__(512, 1)
moe_gemm_h(const float* __restrict__ W_all,      // harness fp32 [E][K][N]
           const float* __restrict__ bias_all) {
    constexpr int NCH = KK / BK;
    extern __shared__ uint32_t smu[];
    uint32_t sb = smem_u32(smu);

    int e = blockIdx.z;
    int cnt = g_count[e];
    int m0 = blockIdx.y * BM;
    if (m0 >= cnt) return;
    int off = expert_offset(e);
    int n0 = blockIdx.x * BN;

    const float* W    = W_all + (size_t)e * KK * NN;
    const float* bias = bias_all + (size_t)e * NN;

    int tid = threadIdx.x;
    int wid = tid >> 5, lane = tid & 31;
    int wm = wid >> 2, wn = wid & 3;        // 4 x 4 warps; warp tile 64(m) x 32(n)
    int g = lane >> 2, tg = lane & 3;

    // ---- A: ONE gathered fp16 row pointer per thread (row = tid/2) ----
    const __half* asrc;
    {
        int r = tid >> 1;
        int gm = m0 + r;
        if (gm > cnt - 1) gm = cnt - 1;     // clamp; masked in epilogue
        int grow = off + gm;
        const __half* base = FFN1 ? (XH + (size_t)g_tok[grow] * KK)
                                  : (HID_H + (size_t)grow * KK);
        asrc = base + (tid & 1) * 16;       // half-row: 16 fp16 = 32 B (2 cp16)
    }
    uint32_t adst0 = sb + (uint32_t)((tid >> 1) * 80 + (tid & 1) * 32);
    constexpr uint32_t STAGE_B = STAGE_U * 4;

    // ldmatrix A base: row = lane&15 within 16-row tile; k-half = lane>>4
    uint32_t a_lm = sb + (uint32_t)(((wm * 64 + (lane & 15)) * A_STR_U
                                     + (lane >> 4) * 4) * 4);

    // ---- B: kpair row = tid/32 (16 rows), col4 = (tid%32)*4 (covers 128) ----
    int bkp = tid >> 5;
    int bn  = (tid & 31) * 4;
    const float* bw0 = W + (size_t)(2 * bkp)     * NN + n0 + bn;
    const float* bw1 = W + (size_t)(2 * bkp + 1) * NN + n0 + bn;
    uint32_t bst_off = (uint32_t)(A_TILE_U + bkp * B_STR_U + bn);

    float acc[4][4][4];
#pragma unroll
    for (int mi = 0; mi < 4; mi++)
#pragma unroll
        for (int ni = 0; ni < 4; ni++)
#pragma unroll
            for (int q = 0; q < 4; q++) acc[mi][ni][q] = 0.f;

    // ---- prologue: fill stage 0 ----
    cp_async16(adst0, asrc);
    cp_async16(adst0 + 16, asrc + 8);
    cp_commit();
    {
        float4 v0 = *reinterpret_cast<const float4*>(bw0);
        float4 v1 = *reinterpret_cast<const float4*>(bw1);
        *reinterpret_cast<uint4*>(smu + bst_off) =
            make_uint4(pack_h2(v0.x, v1.x), pack_h2(v0.y, v1.y),
                       pack_h2(v0.z, v1.z), pack_h2(v0.w, v1.w));
    }
    cp_wait<0>();
    __syncthreads();

#pragma unroll 1
    for (int c = 0; c < NCH; c++) {
        float4 v0, v1;
        bool pf = (c + 1 < NCH);
        uint32_t so = ((c + 1) & 1) * STAGE_B;
        uint32_t* bst = smu + ((c + 1) & 1) * STAGE_U + bst_off;
        size_t brow = (size_t)(c + 1) * BK * NN;
        if (pf) {
            int ka = (c + 1) * BK;
            cp_async16(adst0 + so, asrc + ka);
            cp_async16(adst0 + so + 16, asrc + ka + 8);
            cp_commit();
            v0 = *reinterpret_cast<const float4*>(bw0 + brow);  // hoisted LDGs
            v1 = *reinterpret_cast<const float4*>(bw1 + brow);
        }

        uint32_t a_stage = a_lm + (c & 1) * STAGE_B;
        const uint32_t* Bs = smu + (c & 1) * STAGE_U + A_TILE_U;
#pragma unroll
        for (int kh = 0; kh < 2; kh++) {         // two k=16 steps per BK=32
            uint32_t af[4][4], bf[4][2];
#pragma unroll
            for (int mi = 0; mi < 4; mi++)
                ldsm_x4(af[mi], a_stage + (uint32_t)((mi * 16 * A_STR_U + kh * 8) * 4));
#pragma unroll
            for (int ni = 0; ni < 4; ni++) {
                const uint32_t* bp = Bs + (kh * 8 + tg) * B_STR_U + wn * 32 + ni * 8 + g;
                bf[ni][0] = bp[0];
                bf[ni][1] = bp[4 * B_STR_U];
            }
#pragma unroll
            for (int mi = 0; mi < 4; mi++)
#pragma unroll
                for (int ni = 0; ni < 4; ni++)
                    mma_f16(acc[mi][ni], af[mi], bf[ni]);
        }

        if (pf) {
            *reinterpret_cast<uint4*>(bst) =
                make_uint4(pack_h2(v0.x, v1.x), pack_h2(v0.y, v1.y),
                           pack_h2(v0.z, v1.z), pack_h2(v0.w, v1.w));
            cp_wait<0>();
        }
        __syncthreads();
    }

    // ---- epilogue ----
#pragma unroll
    for (int mi = 0; mi < 4; mi++) {
        int r0 = m0 + wm * 64 + mi * 16 + g;
        int r1 = r0 + 8;
        bool va = r0 < cnt, vb = r1 < cnt;
        size_t row0 = (size_t)(off + r0), row1 = (size_t)(off + r1);
#pragma unroll
        for (int ni = 0; ni < 4; ni++) {
            int col = ni * 8 + 2 * tg;
            float2 bv = *reinterpret_cast<const float2*>(bias + n0 + wn * 32 + col);
            float c00 = acc[mi][ni][0] + bv.x;
            float c01 = acc[mi][ni][1] + bv.y;
            float c10 = acc[mi][ni][2] + bv.x;
            float c11 = acc[mi][ni][3] + bv.y;
            if (FFN1) {
                uint32_t h0 = pack_h2(fmaxf(c00, 0.f), fmaxf(c01, 0.f));
                uint32_t h1 = pack_h2(fmaxf(c10, 0.f), fmaxf(c11, 0.f));
                if (va) *reinterpret_cast<uint32_t*>(
                            HID_H + row0 * NN + n0 + wn * 32 + col) = h0;
                if (vb) *reinterpret_cast<uint32_t*>(
                            HID_H + row1 * NN + n0 + wn * 32 + col) = h1;
            } else {
                if (va) *reinterpret_cast<float2*>(
                            g_y + row0 * NN + n0 + wn * 32 + col) = make_float2(c00, c01);
                if (vb) *reinterpret_cast<float2*>(
                            g_y + row1 * NN + n0 + wn * 32 + col) = make_float2(c10, c11);
            }
        }
    }
}

// ---------------- combine pairs into output ----------------
__global__ void combine_kernel(float* __restrict__ out) {
    int i = blockIdx.x * blockDim.x + threadIdx.x;
    if (i >= T_TOKENS * (DD / 4)) return;
    int t  = i / (DD / 4);
    int d4 = i % (DD / 4);
    int r0 = g_row[t * 2 + 0];
    int r1 = g_row[t * 2 + 1];
    float g0 = g_gate[t * 2 + 0];
    float g1 = g_gate[t * 2 + 1];
    const float4* y0 = reinterpret_cast<const float4*>(g_y + (size_t)r0 * DD);
    const float4* y1 = reinterpret_cast<const float4*>(g_y + (size_t)r1 * DD);
    float4 a = y0[d4], b = y1[d4], o;
    o.x = g0 * a.x + g1 * b.x;
    o.y = g0 * a.y + g1 * b.y;
    o.z = g0 * a.z + g1 * b.z;
    o.w = g0 * a.w + g1 * b.w;
    reinterpret_cast<float4*>(out)[i] = o;
}

// ---------------- launch ----------------
extern "C" void kernel_launch(void* const* d_in, const int* in_sizes, int n_in,
                              void* d_out, int out_size) {
    const float* x  = (const float*)d_in[0];
    const float* wr = (const float*)d_in[1];
    const float* br = (const float*)d_in[2];
    const float* w1 = (const float*)d_in[3];
    const float* b1 = (const float*)d_in[4];
    const float* w2 = (const float*)d_in[5];
    const float* b2 = (const float*)d_in[6];
    float* out = (float*)d_out;

    cudaFuncSetAttribute(moe_gemm_h<HH, DD, true>,
                         cudaFuncAttributeMaxDynamicSharedMemorySize, GEMM_SMEM);
    cudaFuncSetAttribute(moe_gemm_h<DD, HH, false>,
                         cudaFuncAttributeMaxDynamicSharedMemorySize, GEMM_SMEM);

    zero_counts_kernel<<<1, 32>>>();
    router_kernel<<<T_TOKENS / 8, 256>>>(x, wr, br);   // also writes x fp16
    scatter_kernel<<<PAIRS / 256, 256>>>();

    // FFN1: N=4096, K=1024 (B from harness w1, converted in-kernel)
    {
        dim3 grid(HH / BN, 8192 / BM, EE);
        moe_gemm_h<HH, DD, true><<<grid, 512, GEMM_SMEM>>>(w1, b1);
    }
    // FFN2: N=1024, K=4096 (B from harness w2)
    {
        dim3 grid(DD / BN, 8192 / BM, EE);
        moe_gemm_h<DD, HH, false><<<grid, 512, GEMM_SMEM>>>(w2, b2);
    }

    combine_kernel<<<(T_TOKENS * (DD / 4)) / 256, 256>>>(out);
}

// round 16
// speedup vs baseline: 1.3549x; 1.3549x over previous
#include <cuda_runtime.h>
#include <cuda_fp16.h>
#include <stdint.h>
#include <math.h>

// ---------------- problem constants ----------------
#define T_TOKENS 8192          // 4 * 2048
#define DD 1024                // emb dim
#define HH 4096                // hidden dim
#define EE 8                   // experts
#define PAIRS (T_TOKENS * 2)   // 16384 routed (token, expert) pairs

// ---------------- device scratch: proven footprint; NO weight copies ----------
__device__ int   g_count[EE];
__device__ int   g_ek[PAIRS];
__device__ int   g_slot[PAIRS];
__device__ float g_gate[PAIRS];
__device__ int   g_row[PAIRS];     // per (t,k): compact row id
__device__ int   g_tok[PAIRS];     // per compact row: token id
__device__ float g_hid[(size_t)PAIRS * HH];     // head 134 MB used as fp16 hid
__device__ float g_y  [(size_t)PAIRS * DD];     // head 16.7 MB = x fp16 alias

#define HID_H   (reinterpret_cast<__half*>(g_hid))
#define XH      (reinterpret_cast<__half*>(g_y))

// ---------------- helpers ----------------
__device__ __forceinline__ uint32_t smem_u32(const void* p) {
    uint32_t a;
    asm("{ .reg .u64 t; cvta.to.shared.u64 t, %1; cvt.u32.u64 %0, t; }" : "=r"(a) : "l"(p));
    return a;
}
__device__ __forceinline__ void cp_async16(uint32_t dst, const void* src) {
    asm volatile("cp.async.cg.shared.global [%0], [%1], 16;" :: "r"(dst), "l"(src));
}
__device__ __forceinline__ void cp_commit() {
    asm volatile("cp.async.commit_group;" ::: "memory");
}
template <int N>
__device__ __forceinline__ void cp_wait() {
    asm volatile("cp.async.wait_group %0;" :: "n"(N) : "memory");
}
__device__ __forceinline__ uint32_t pack_h2(float lo, float hi) {
    __half2 h = __floats2half2_rn(lo, hi);      // low 16 bits = lo
    return *reinterpret_cast<uint32_t*>(&h);
}
__device__ __forceinline__ void mma_f16(float* d, const uint32_t* a, const uint32_t* b) {
    asm volatile(
        "mma.sync.aligned.m16n8k16.row.col.f32.f16.f16.f32 "
        "{%0,%1,%2,%3}, {%4,%5,%6,%7}, {%8,%9}, {%0,%1,%2,%3};"
        : "+f"(d[0]), "+f"(d[1]), "+f"(d[2]), "+f"(d[3])
        : "r"(a[0]), "r"(a[1]), "r"(a[2]), "r"(a[3]), "r"(b[0]), "r"(b[1]));
}
__device__ __forceinline__ void ldsm_x4(uint32_t* r, uint32_t addr) {
    asm volatile("ldmatrix.sync.aligned.m8n8.x4.shared.b16 {%0,%1,%2,%3}, [%4];"
                 : "=r"(r[0]), "=r"(r[1]), "=r"(r[2]), "=r"(r[3]) : "r"(addr));
}
__device__ __forceinline__ int expert_offset(int e) {
    int s = 0;
#pragma unroll
    for (int i = 0; i < EE; i++) if (i < e) s += g_count[i];
    return s;
}

// ---------------- kernel 0: zero counters ----------------
__global__ void zero_counts_kernel() {
    if (threadIdx.x < EE) g_count[threadIdx.x] = 0;
}

// ---------------- kernel 1: router (1 warp/token) + fused x->fp16 ------------
__global__ void router_kernel(const float* __restrict__ x,
                              const float* __restrict__ wr,
                              const float* __restrict__ br) {
    int warp = (blockIdx.x * blockDim.x + threadIdx.x) >> 5;
    int lane = threadIdx.x & 31;
    if (warp >= T_TOKENS) return;
    const float* xr = x + (size_t)warp * DD;
    __half* xh = XH + (size_t)warp * DD;

    float acc[EE];
#pragma unroll
    for (int e = 0; e < EE; e++) acc[e] = 0.f;
#pragma unroll 4
    for (int c = 0; c < DD / 32; c++) {
        int k = c * 32 + lane;
        float xv = __ldg(xr + k);
        xh[k] = __float2half_rn(xv);             // fused fp16 conversion
        const float4* w4 = reinterpret_cast<const float4*>(wr + (size_t)k * EE);
        float4 a = __ldg(&w4[0]);
        float4 b = __ldg(&w4[1]);
        acc[0] += xv * a.x; acc[1] += xv * a.y; acc[2] += xv * a.z; acc[3] += xv * a.w;
        acc[4] += xv * b.x; acc[5] += xv * b.y; acc[6] += xv * b.z; acc[7] += xv * b.w;
    }
#pragma unroll
    for (int e = 0; e < EE; e++)
#pragma unroll
        for (int o = 16; o > 0; o >>= 1)
            acc[e] += __shfl_down_sync(0xffffffffu, acc[e], o);

    if (lane == 0) {
        float l[EE];
        float mx = -1e30f;
#pragma unroll
        for (int e = 0; e < EE; e++) { l[e] = acc[e] + br[e]; mx = fmaxf(mx, l[e]); }
        float s = 0.f;
#pragma unroll
        for (int e = 0; e < EE; e++) { l[e] = expf(l[e] - mx); s += l[e]; }
        float inv = 1.0f / s;
        int e0 = 0;
#pragma unroll
        for (int e = 1; e < EE; e++) if (l[e] > l[e0]) e0 = e;
        int e1 = (e0 == 0) ? 1 : 0;
#pragma unroll
        for (int e = 0; e < EE; e++) if (e != e0 && l[e] > l[e1]) e1 = e;
        int t = warp;
        int s0 = atomicAdd(&g_count[e0], 1);
        g_ek[t * 2 + 0] = e0; g_slot[t * 2 + 0] = s0; g_gate[t * 2 + 0] = l[e0] * inv;
        int s1 = atomicAdd(&g_count[e1], 1);
        g_ek[t * 2 + 1] = e1; g_slot[t * 2 + 1] = s1; g_gate[t * 2 + 1] = l[e1] * inv;
    }
}

// ---------------- kernel 2: scatter compact rows (offsets inline) ------------
__global__ void scatter_kernel() {
    int i = blockIdx.x * blockDim.x + threadIdx.x;
    if (i >= PAIRS) return;
    int e = g_ek[i];
    int row = expert_offset(e) + g_slot[i];
    g_row[i] = row;
    g_tok[row] = i >> 1;
}

// ---------------- grouped GEMM: m16n8k16 fp16, LDSM A, 3-stage A pipeline ----
// R14 geometry: CTA 128x128x32, 2x4 warps of 64x32, occ 2.
// A: THREE cp.async smem stages -> A(c+1) issued a full chunk early, latency
//    fully covered. B: 2 smem stages, LDG fp32 hoisted before MMAs (R14 path).
constexpr int BM = 128, BN = 128, BK = 32;   // BK in k-elements
constexpr int A_STR_U = 20;                  // 40 fp16 = 80 B row stride
constexpr int B_STR_U = 136;                 // u32 stride per k-pair row
constexpr int A_TILE_U = BM * A_STR_U;       // 2560 u32 (10240 B)
constexpr int B_TILE_U = (BK / 2) * B_STR_U; // 2176 u32 (8704 B)
constexpr int BBASE_U  = 3 * A_TILE_U;       // B region after 3 A stages
constexpr int GEMM_SMEM = (3 * A_TILE_U + 2 * B_TILE_U) * 4;   // 48128 bytes
constexpr uint32_t A_STAGE_B = A_TILE_U * 4;

template <int NN, int KK, bool FFN1>
__global__ void __launch_bounds__(256, 2)
moe_gemm_h(const float* __restrict__ W_all,      // harness fp32 [E][K][N]
           const float* __restrict__ bias_all) {
    constexpr int NCH = KK / BK;
    extern __shared__ uint32_t smu[];
    uint32_t sb = smem_u32(smu);

    int e = blockIdx.z;
    int cnt = g_count[e];
    int m0 = blockIdx.y * BM;
    if (m0 >= cnt) return;
    int off = expert_offset(e);
    int n0 = blockIdx.x * BN;

    const float* W    = W_all + (size_t)e * KK * NN;
    const float* bias = bias_all + (size_t)e * NN;

    int tid = threadIdx.x;
    int wid = tid >> 5, lane = tid & 31;
    int wm = wid >> 2, wn = wid & 3;        // 2 x 4 warps; warp tile 64(m) x 32(n)
    int g = lane >> 2, tg = lane & 3;

    // ---- A: 2 gathered fp16 row pointers per thread ----
    const __half* asrc[2];
#pragma unroll
    for (int i = 0; i < 2; i++) {
        int r = i * 64 + (tid >> 2);
        int gm = m0 + r;
        if (gm > cnt - 1) gm = cnt - 1;     // clamp; masked in epilogue
        int grow = off + gm;
        const __half* base = FFN1 ? (XH + (size_t)g_tok[grow] * KK)
                                  : (HID_H + (size_t)grow * KK);
        asrc[i] = base + (tid & 3) * 8;
    }
    uint32_t adst0 = sb + (uint32_t)((tid >> 2) * 80 + (tid & 3) * 16);

    // ldmatrix A base: row = lane&15 within 16-row tile; k-half = lane>>4
    uint32_t a_lm = sb + (uint32_t)(((wm * 64 + (lane & 15)) * A_STR_U
                                     + (lane >> 4) * 4) * 4);

    // ---- B: per-thread LDG mapping. kpair row = tid/16, n = (tid%16)*4 + {0,64}
    int bkp = tid >> 4;
    int bn  = (tid & 15) * 4;
    const float* bw0 = W + (size_t)(2 * bkp)     * NN + n0 + bn;
    const float* bw1 = W + (size_t)(2 * bkp + 1) * NN + n0 + bn;
    uint32_t bst_off = (uint32_t)(BBASE_U + bkp * B_STR_U + bn);

    float acc[4][4][4];
#pragma unroll
    for (int mi = 0; mi < 4; mi++)
#pragma unroll
        for (int ni = 0; ni < 4; ni++)
#pragma unroll
            for (int q = 0; q < 4; q++) acc[mi][ni][q] = 0.f;

    // ---- prologue: A stages 0 and 1 as separate groups; B stage 0 ----
#pragma unroll
    for (int s = 0; s < 2; s++) {
        int ka = s * BK;
#pragma unroll
        for (int i = 0; i < 2; i++)
            cp_async16(adst0 + s * A_STAGE_B + i * (64 * 80), asrc[i] + ka);
        cp_commit();
    }
    {
        float4 v0 = *reinterpret_cast<const float4*>(bw0);
        float4 v1 = *reinterpret_cast<const float4*>(bw1);
        float4 u0 = *reinterpret_cast<const float4*>(bw0 + 64);
        float4 u1 = *reinterpret_cast<const float4*>(bw1 + 64);
        *reinterpret_cast<uint4*>(smu + bst_off) =
            make_uint4(pack_h2(v0.x, v1.x), pack_h2(v0.y, v1.y),
                       pack_h2(v0.z, v1.z), pack_h2(v0.w, v1.w));
        *reinterpret_cast<uint4*>(smu + bst_off + 64) =
            make_uint4(pack_h2(u0.x, u1.x), pack_h2(u0.y, u1.y),
                       pack_h2(u0.z, u1.z), pack_h2(u0.w, u1.w));
    }
    cp_wait<1>();                            // A(0) done; A(1) may be in flight
    __syncthreads();

    int sa = 0, sw = 2;                      // A read / write stage (mod 3)
#pragma unroll 1
    for (int c = 0; c < NCH; c++) {
        float4 v0, v1, u0, u1;
        bool pf  = (c + 1 < NCH);
        bool pfA = (c + 2 < NCH);
        uint32_t* bst = smu + ((c + 1) & 1) * B_TILE_U + bst_off;
        size_t brow = (size_t)(c + 1) * BK * NN;
        if (pfA) {
            int ka = (c + 2) * BK;
#pragma unroll
            for (int i = 0; i < 2; i++)
                cp_async16(adst0 + sw * A_STAGE_B + i * (64 * 80), asrc[i] + ka);
        }
        cp_commit();                          // one group per iteration (may be empty)
        if (pf) {
            v0 = *reinterpret_cast<const float4*>(bw0 + brow);   // hoisted B LDGs
            v1 = *reinterpret_cast<const float4*>(bw1 + brow);
            u0 = *reinterpret_cast<const float4*>(bw0 + brow + 64);
            u1 = *reinterpret_cast<const float4*>(bw1 + brow + 64);
        }

        uint32_t a_stage = a_lm + sa * A_STAGE_B;
        const uint32_t* Bs = smu + BBASE_U + (c & 1) * B_TILE_U;
#pragma unroll
        for (int kh = 0; kh < 2; kh++) {         // two k=16 steps per BK=32
            uint32_t af[4][4], bf[4][2];
#pragma unroll
            for (int mi = 0; mi < 4; mi++)
                ldsm_x4(af[mi], a_stage + (uint32_t)((mi * 16 * A_STR_U + kh * 8) * 4));
#pragma unroll
            for (int ni = 0; ni < 4; ni++) {
                const uint32_t* bp = Bs + (kh * 8 + tg) * B_STR_U + wn * 32 + ni * 8 + g
                                     - BBASE_U + BBASE_U;  // (kept simple)
                bf[ni][0] = bp[0];
                bf[ni][1] = bp[4 * B_STR_U];
            }
#pragma unroll
            for (int mi = 0; mi < 4; mi++)
#pragma unroll
                for (int ni = 0; ni < 4; ni++)
                    mma_f16(acc[mi][ni], af[mi], bf[ni]);
        }

        if (pf) {
            *reinterpret_cast<uint4*>(bst) =
                make_uint4(pack_h2(v0.x, v1.x), pack_h2(v0.y, v1.y),
                           pack_h2(v0.z, v1.z), pack_h2(v0.w, v1.w));
            *reinterpret_cast<uint4*>(bst + 64) =
                make_uint4(pack_h2(u0.x, u1.x), pack_h2(u0.y, u1.y),
                           pack_h2(u0.z, u1.z), pack_h2(u0.w, u1.w));
        }
        cp_wait<1>();                         // A(c+1) complete; A(c+2) in flight
        __syncthreads();
        sa = (sa == 2) ? 0 : sa + 1;
        sw = (sw == 2) ? 0 : sw + 1;
    }

    // ---- epilogue ----
#pragma unroll
    for (int mi = 0; mi < 4; mi++) {
        int r0 = m0 + wm * 64 + mi * 16 + g;
        int r1 = r0 + 8;
        bool va = r0 < cnt, vb = r1 < cnt;
        size_t row0 = (size_t)(off + r0), row1 = (size_t)(off + r1);
#pragma unroll
        for (int ni = 0; ni < 4; ni++) {
            int col = ni * 8 + 2 * tg;
            float2 bv = *reinterpret_cast<const float2*>(bias + n0 + wn * 32 + col);
            float c00 = acc[mi][ni][0] + bv.x;
            float c01 = acc[mi][ni][1] + bv.y;
            float c10 = acc[mi][ni][2] + bv.x;
            float c11 = acc[mi][ni][3] + bv.y;
            if (FFN1) {
                uint32_t h0 = pack_h2(fmaxf(c00, 0.f), fmaxf(c01, 0.f));
                uint32_t h1 = pack_h2(fmaxf(c10, 0.f), fmaxf(c11, 0.f));
                if (va) *reinterpret_cast<uint32_t*>(
                            HID_H + row0 * NN + n0 + wn * 32 + col) = h0;
                if (vb) *reinterpret_cast<uint32_t*>(
                            HID_H + row1 * NN + n0 + wn * 32 + col) = h1;
            } else {
                if (va) *reinterpret_cast<float2*>(
                            g_y + row0 * NN + n0 + wn * 32 + col) = make_float2(c00, c01);
                if (vb) *reinterpret_cast<float2*>(
                            g_y + row1 * NN + n0 + wn * 32 + col) = make_float2(c10, c11);
            }
        }
    }
}

// ---------------- combine pairs into output ----------------
__global__ void combine_kernel(float* __restrict__ out) {
    int i = blockIdx.x * blockDim.x + threadIdx.x;
    if (i >= T_TOKENS * (DD / 4)) return;
    int t  = i / (DD / 4);
    int d4 = i % (DD / 4);
    int r0 = g_row[t * 2 + 0];
    int r1 = g_row[t * 2 + 1];
    float g0 = g_gate[t * 2 + 0];
    float g1 = g_gate[t * 2 + 1];
    const float4* y0 = reinterpret_cast<const float4*>(g_y + (size_t)r0 * DD);
    const float4* y1 = reinterpret_cast<const float4*>(g_y + (size_t)r1 * DD);
    float4 a = y0[d4], b = y1[d4], o;
    o.x = g0 * a.x + g1 * b.x;
    o.y = g0 * a.y + g1 * b.y;
    o.z = g0 * a.z + g1 * b.z;
    o.w = g0 * a.w + g1 * b.w;
    reinterpret_cast<float4*>(out)[i] = o;
}

// ---------------- launch ----------------
extern "C" void kernel_launch(void* const* d_in, const int* in_sizes, int n_in,
                              void* d_out, int out_size) {
    const float* x  = (const float*)d_in[0];
    const float* wr = (const float*)d_in[1];
    const float* br = (const float*)d_in[2];
    const float* w1 = (const float*)d_in[3];
    const float* b1 = (const float*)d_in[4];
    const float* w2 = (const float*)d_in[5];
    const float* b2 = (const float*)d_in[6];
    float* out = (float*)d_out;

    cudaFuncSetAttribute(moe_gemm_h<HH, DD, true>,
                         cudaFuncAttributeMaxDynamicSharedMemorySize, GEMM_SMEM);
    cudaFuncSetAttribute(moe_gemm_h<DD, HH, false>,
                         cudaFuncAttributeMaxDynamicSharedMemorySize, GEMM_SMEM);

    zero_counts_kernel<<<1, 32>>>();
    router_kernel<<<T_TOKENS / 8, 256>>>(x, wr, br);   // also writes x fp16
    scatter_kernel<<<PAIRS / 256, 256>>>();

    // FFN1: N=4096, K=1024 (B from harness w1, converted in-kernel)
    {
        dim3 grid(HH / BN, 8192 / BM, EE);
        moe_gemm_h<HH, DD, true><<<grid, 256, GEMM_SMEM>>>(w1, b1);
    }
    // FFN2: N=1024, K=4096 (B from harness w2)
    {
        dim3 grid(DD / BN, 8192 / BM, EE);
        moe_gemm_h<DD, HH, false><<<grid, 256, GEMM_SMEM>>>(w2, b2);
    }

    combine_kernel<<<(T_TOKENS * (DD / 4)) / 256, 256>>>(out);
}